// round 4
// baseline (speedup 1.0000x reference)
#include <cuda_runtime.h>
#include <cstdint>

// ---------------- problem constants ----------------
#define B_    4
#define N_    1024
#define CIN_  256
#define HW_   256         // feature map H = W = 256
#define D_    512
#define IN_   2304        // CIN * 3 * 3
#define ROWS_ 4096        // B * N

// ---------------- device scratch ----------------
__device__ float g_featsT[(size_t)B_ * HW_ * HW_ * CIN_]; // NHWC, 256 MB
__device__ float g_bbox[ROWS_ * 4];
__device__ float g_flat[(size_t)ROWS_ * IN_];              // 37.7 MB
__device__ float g_hidden[(size_t)ROWS_ * D_];             // 8 MB
__device__ float g_lines[(size_t)ROWS_ * D_];              // 8 MB
__device__ float g_outt[(size_t)ROWS_ * D_];               // 8 MB (B,N,D)

// ---------------- f32x2 helpers ----------------
__device__ __forceinline__ void fma2(unsigned long long& d,
                                     unsigned long long a,
                                     unsigned long long b) {
    asm("fma.rn.f32x2 %0, %1, %2, %0;" : "+l"(d) : "l"(a), "l"(b));
}
__device__ __forceinline__ float2 unpack2(unsigned long long v) {
    float2 r;
    asm("mov.b64 {%0, %1}, %2;" : "=f"(r.x), "=f"(r.y) : "l"(v));
    return r;
}

// ---------------- kernel 1: bbox from 4-corner boxes ----------------
__global__ void bbox_kernel(const float* __restrict__ boxes) {
    int n = blockIdx.x * blockDim.x + threadIdx.x;
    if (n >= ROWS_) return;
    const float* p = boxes + (size_t)n * 8;
    float x0 = p[0], y0 = p[1], x1 = p[2], y1 = p[3];
    float x2 = p[4], y2 = p[5], x3 = p[6], y3 = p[7];
    g_bbox[n * 4 + 0] = fminf(fminf(x0, x1), fminf(x2, x3));
    g_bbox[n * 4 + 1] = fminf(fminf(y0, y1), fminf(y2, y3));
    g_bbox[n * 4 + 2] = fmaxf(fmaxf(x0, x1), fmaxf(x2, x3));
    g_bbox[n * 4 + 3] = fmaxf(fmaxf(y0, y1), fmaxf(y2, y3));
}

// ---------------- kernel 2: NCHW -> NHWC transpose of feats ----------------
__global__ void feat_transpose_kernel(const float* __restrict__ in) {
    __shared__ float tile[32][33];
    int b  = blockIdx.z;
    int p0 = blockIdx.x * 32;
    int c0 = blockIdx.y * 32;
    const float* ib = in + (size_t)b * CIN_ * (HW_ * HW_);
    float* ob = g_featsT + (size_t)b * (HW_ * HW_) * CIN_;
    int tx = threadIdx.x, ty = threadIdx.y;
#pragma unroll
    for (int i = 0; i < 4; i++)
        tile[ty + i * 8][tx] = ib[(size_t)(c0 + ty + i * 8) * (HW_ * HW_) + p0 + tx];
    __syncthreads();
#pragma unroll
    for (int i = 0; i < 4; i++)
        ob[(size_t)(p0 + ty + i * 8) * CIN_ + c0 + tx] = tile[tx][ty + i * 8];
}

// ---------------- kernel 3: ROI align -> g_flat ----------------
__global__ __launch_bounds__(256) void roi_kernel() {
    int n = blockIdx.x;          // 0..4095
    int b = n >> 10;
    int c = threadIdx.x;         // channel 0..255
    const float* fb = g_featsT + (size_t)b * (HW_ * HW_) * CIN_;

    float4 bb = *(const float4*)(g_bbox + n * 4);
    float x1 = bb.x * 0.25f, y1 = bb.y * 0.25f;
    float x2 = bb.z * 0.25f, y2 = bb.w * 0.25f;
    float binw = fmaxf(x2 - x1, 1.0f) * (1.0f / 3.0f);
    float binh = fmaxf(y2 - y1, 1.0f) * (1.0f / 3.0f);

    int   yi0[6], yi1[6], xi0[6], xi1[6];
    float yl[6], yv[6], xl[6], xv[6];
#pragma unroll
    for (int s = 0; s < 6; s++) {
        float g = 0.5f * (float)s + 0.25f;
        float yy = y1 + g * binh;
        yv[s] = (yy > -1.0f && yy < 256.0f) ? 1.0f : 0.0f;
        float yc = fminf(fmaxf(yy, 0.0f), 255.0f);
        int i0 = (int)floorf(yc);
        yi0[s] = i0; yi1[s] = min(i0 + 1, 255); yl[s] = yc - (float)i0;

        float xx = x1 + g * binw;
        xv[s] = (xx > -1.0f && xx < 256.0f) ? 1.0f : 0.0f;
        float xc = fminf(fmaxf(xx, 0.0f), 255.0f);
        int j0 = (int)floorf(xc);
        xi0[s] = j0; xi1[s] = min(j0 + 1, 255); xl[s] = xc - (float)j0;
    }

    float acc[9];
#pragma unroll
    for (int i = 0; i < 9; i++) acc[i] = 0.0f;

#pragma unroll
    for (int sy = 0; sy < 6; sy++) {
        float ly = yl[sy], hy = 1.0f - ly;
        int r0 = yi0[sy] * 256, r1 = yi1[sy] * 256;
#pragma unroll
        for (int sx = 0; sx < 6; sx++) {
            float lx = xl[sx], hx = 1.0f - lx;
            float w = 0.25f * yv[sy] * xv[sx];
            const float* p00 = fb + ((size_t)(r0 + xi0[sx])) * CIN_ + c;
            const float* p01 = fb + ((size_t)(r0 + xi1[sx])) * CIN_ + c;
            const float* p10 = fb + ((size_t)(r1 + xi0[sx])) * CIN_ + c;
            const float* p11 = fb + ((size_t)(r1 + xi1[sx])) * CIN_ + c;
            float v = __ldg(p00) * (hy * hx) + __ldg(p01) * (hy * lx)
                    + __ldg(p10) * (ly * hx) + __ldg(p11) * (ly * lx);
            acc[(sy >> 1) * 3 + (sx >> 1)] += v * w;
        }
    }

    __shared__ float st[IN_];
#pragma unroll
    for (int i = 0; i < 9; i++) st[c * 9 + i] = acc[i];
    __syncthreads();
    float* dst = g_flat + (size_t)n * IN_;
    for (int i = c; i < IN_; i += 256) dst[i] = st[i];
}

// ---------------- kernel 4/5: fp32 GEMM, 64x128x16 tiles ---------------
// A duplicated in smem -> both FMA2 operands come straight from LDS.128.
// MODE 0: g_hidden = relu(g_flat @ W1 + b1), K = 2304
// MODE 1: g_lines  =        g_hidden @ W2 + b2, K = 512
#define BM 64
#define BN 128
#define BK 16

template <int MODE>
__global__ __launch_bounds__(256, 2) void gemm_kernel(const float* __restrict__ Bw,
                                                      const float* __restrict__ bias) {
    constexpr int K = (MODE == 0) ? IN_ : D_;
    const float* A = (MODE == 0) ? g_flat : g_hidden;
    float* C       = (MODE == 0) ? g_hidden : g_lines;

    __shared__ float As[2][BK][2 * BM + 4];   // k-major, each A value duplicated
    __shared__ float Bs[2][BK][BN];

    const int tid = threadIdx.x;
    const int bm = blockIdx.y * BM;
    const int bn = blockIdx.x * BN;
    const int ty = tid >> 4;        // 0..15 -> 4 rows each
    const int tx = tid & 15;        // 0..15 -> 8 cols each

    // global loaders
    const int arow = tid >> 2;            // 0..63
    const int akq  = (tid & 3) * 4;       // 0,4,8,12
    const int bk   = tid >> 4;            // 0..15
    const int bnq  = (tid & 15) * 8;      // 0..120

    const float* Aptr = A + (size_t)(bm + arow) * K + akq;
    const float* Bptr = Bw + (size_t)bk * D_ + bn + bnq;

    unsigned long long acc[4][4];
#pragma unroll
    for (int i = 0; i < 4; i++)
#pragma unroll
        for (int j = 0; j < 4; j++) acc[i][j] = 0ULL;

    // prefetch tile 0
    float4 pa  = *(const float4*)(Aptr);
    float4 pb0 = *(const float4*)(Bptr);
    float4 pb1 = *(const float4*)(Bptr + 4);

    // store tile 0 (A duplicated)
    {
        float2* d0 = (float2*)&As[0][akq + 0][2 * arow];
        float2* d1 = (float2*)&As[0][akq + 1][2 * arow];
        float2* d2 = (float2*)&As[0][akq + 2][2 * arow];
        float2* d3 = (float2*)&As[0][akq + 3][2 * arow];
        *d0 = make_float2(pa.x, pa.x);
        *d1 = make_float2(pa.y, pa.y);
        *d2 = make_float2(pa.z, pa.z);
        *d3 = make_float2(pa.w, pa.w);
        *(float4*)&Bs[0][bk][bnq]     = pb0;
        *(float4*)&Bs[0][bk][bnq + 4] = pb1;
    }
    __syncthreads();

    int buf = 0;
    for (int k0 = 0; k0 < K; k0 += BK) {
        const bool has_next = (k0 + BK < K);
        if (has_next) {
            pa  = *(const float4*)(Aptr + k0 + BK);
            pb0 = *(const float4*)(Bptr + (size_t)(k0 + BK) * D_);
            pb1 = *(const float4*)(Bptr + (size_t)(k0 + BK) * D_ + 4);
        }

#pragma unroll
        for (int k = 0; k < BK; k++) {
            float4 a0 = *(const float4*)&As[buf][k][ty * 8];
            float4 a1 = *(const float4*)&As[buf][k][ty * 8 + 4];
            float4 b0 = *(const float4*)&Bs[buf][k][tx * 8];
            float4 b1 = *(const float4*)&Bs[buf][k][tx * 8 + 4];
            union { float4 f; unsigned long long u[2]; } ua0, ua1, ub0, ub1;
            ua0.f = a0; ua1.f = a1; ub0.f = b0; ub1.f = b1;
            unsigned long long av[4] = {ua0.u[0], ua0.u[1], ua1.u[0], ua1.u[1]};
            unsigned long long bv[4] = {ub0.u[0], ub0.u[1], ub1.u[0], ub1.u[1]};
#pragma unroll
            for (int i = 0; i < 4; i++)
#pragma unroll
                for (int j = 0; j < 4; j++) fma2(acc[i][j], av[i], bv[j]);
        }

        if (has_next) {
            buf ^= 1;
            float2* d0 = (float2*)&As[buf][akq + 0][2 * arow];
            float2* d1 = (float2*)&As[buf][akq + 1][2 * arow];
            float2* d2 = (float2*)&As[buf][akq + 2][2 * arow];
            float2* d3 = (float2*)&As[buf][akq + 3][2 * arow];
            *d0 = make_float2(pa.x, pa.x);
            *d1 = make_float2(pa.y, pa.y);
            *d2 = make_float2(pa.z, pa.z);
            *d3 = make_float2(pa.w, pa.w);
            *(float4*)&Bs[buf][bk][bnq]     = pb0;
            *(float4*)&Bs[buf][bk][bnq + 4] = pb1;
            __syncthreads();
        }
    }

    // epilogue: coalesced float4 stores
    const int col0 = bn + tx * 8;
    float bias8[8];
#pragma unroll
    for (int j = 0; j < 8; j++) bias8[j] = bias[col0 + j];

#pragma unroll
    for (int i = 0; i < 4; i++) {
        const int row = bm + ty * 4 + i;
        float o[8];
#pragma unroll
        for (int j = 0; j < 4; j++) {
            float2 v = unpack2(acc[i][j]);
            o[2 * j]     = v.x + bias8[2 * j];
            o[2 * j + 1] = v.y + bias8[2 * j + 1];
        }
        if (MODE == 0) {
#pragma unroll
            for (int j = 0; j < 8; j++) o[j] = fmaxf(o[j], 0.0f);
        }
        float* dst = C + (size_t)row * D_ + col0;
        *(float4*)(dst)     = make_float4(o[0], o[1], o[2], o[3]);
        *(float4*)(dst + 4) = make_float4(o[4], o[5], o[6], o[7]);
    }
}

// ---------------- kernel 6: pos embed + LN1 + add + LN2 ----------------
__device__ __forceinline__ float2 block_reduce2(float v0, float v1) {
    __shared__ float s0[16], s1[16];
    int lane = threadIdx.x & 31, wid = threadIdx.x >> 5;
    __syncthreads();
#pragma unroll
    for (int o = 16; o > 0; o >>= 1) {
        v0 += __shfl_down_sync(0xffffffffu, v0, o);
        v1 += __shfl_down_sync(0xffffffffu, v1, o);
    }
    if (lane == 0) { s0[wid] = v0; s1[wid] = v1; }
    __syncthreads();
    if (wid == 0) {
        v0 = (lane < 16) ? s0[lane] : 0.0f;
        v1 = (lane < 16) ? s1[lane] : 0.0f;
#pragma unroll
        for (int o = 8; o > 0; o >>= 1) {
            v0 += __shfl_down_sync(0xffffffffu, v0, o);
            v1 += __shfl_down_sync(0xffffffffu, v1, o);
        }
        if (lane == 0) { s0[0] = v0; s1[0] = v1; }
    }
    __syncthreads();
    return make_float2(s0[0], s1[0]);
}

__global__ __launch_bounds__(512) void posln_kernel(
    const float* __restrict__ img_sizes,
    const float* __restrict__ Wb, const float* __restrict__ bbv,
    const float* __restrict__ g1, const float* __restrict__ be1,
    const float* __restrict__ g2, const float* __restrict__ be2) {
    int n = blockIdx.x;
    int b = n >> 10;
    int d = threadIdx.x;

    float s0 = img_sizes[2 * b], s1 = img_sizes[2 * b + 1];
    float q0 = g_bbox[n * 4 + 0] / s0;
    float q1 = g_bbox[n * 4 + 1] / s1;
    float q2 = g_bbox[n * 4 + 2] / s0;
    float q3 = g_bbox[n * 4 + 3] / s1;

    float p = bbv[d] + q0 * Wb[d] + q1 * Wb[D_ + d] + q2 * Wb[2 * D_ + d] + q3 * Wb[3 * D_ + d];
    float2 r = block_reduce2(p, p * p);
    float mu  = r.x * (1.0f / D_);
    float var = r.y * (1.0f / D_) - mu * mu;
    float pos = (p - mu) * rsqrtf(var + 1e-5f) * g1[d] + be1[d];

    float sf = g_lines[(size_t)n * D_ + d] + pos;
    r = block_reduce2(sf, sf * sf);
    mu  = r.x * (1.0f / D_);
    var = r.y * (1.0f / D_) - mu * mu;
    float o = (sf - mu) * rsqrtf(var + 1e-5f) * g2[d] + be2[d];
    g_outt[(size_t)n * D_ + d] = o;
}

// ---------------- kernel 7: (B,N,D) -> (B,D,N) into d_out ----------------
__global__ void out_transpose_kernel(float* __restrict__ out) {
    __shared__ float tile[32][33];
    int b  = blockIdx.z;
    int n0 = blockIdx.x * 32;
    int d0 = blockIdx.y * 32;
    int tx = threadIdx.x, ty = threadIdx.y;
#pragma unroll
    for (int i = 0; i < 4; i++)
        tile[ty + i * 8][tx] = g_outt[((size_t)(b << 10) + n0 + ty + i * 8) * D_ + d0 + tx];
    __syncthreads();
#pragma unroll
    for (int i = 0; i < 4; i++)
        out[((size_t)b * D_ + d0 + ty + i * 8) * N_ + n0 + tx] = tile[tx][ty + i * 8];
}

// ---------------- kernel 8: masks = 1 ----------------
__global__ void masks_kernel(float* __restrict__ m) {
    int i = blockIdx.x * blockDim.x + threadIdx.x;
    if (i < B_ * N_) m[i] = 1.0f;
}

// ---------------- launch ----------------
extern "C" void kernel_launch(void* const* d_in, const int* in_sizes, int n_in,
                              void* d_out, int out_size) {
    const float* feats     = (const float*)d_in[0];
    const float* boxes     = (const float*)d_in[1];
    const float* img_sizes = (const float*)d_in[2];
    const float* W1 = (const float*)d_in[3];
    const float* b1 = (const float*)d_in[4];
    const float* W2 = (const float*)d_in[5];
    const float* b2 = (const float*)d_in[6];
    const float* Wb = (const float*)d_in[7];
    const float* bb = (const float*)d_in[8];
    const float* g1 = (const float*)d_in[9];
    const float* be1 = (const float*)d_in[10];
    const float* g2 = (const float*)d_in[11];
    const float* be2 = (const float*)d_in[12];
    float* out = (float*)d_out;

    bbox_kernel<<<16, 256>>>(boxes);
    feat_transpose_kernel<<<dim3(2048, 8, 4), dim3(32, 8)>>>(feats);
    roi_kernel<<<ROWS_, 256>>>();
    gemm_kernel<0><<<dim3(D_ / BN, ROWS_ / BM), 256>>>(W1, b1);
    gemm_kernel<1><<<dim3(D_ / BN, ROWS_ / BM), 256>>>(W2, b2);
    posln_kernel<<<ROWS_, 512>>>(img_sizes, Wb, bb, g1, be1, g2, be2);
    out_transpose_kernel<<<dim3(32, 16, 4), dim3(32, 8)>>>(out);
    masks_kernel<<<16, 256>>>(out + (size_t)B_ * D_ * N_);
}

// round 5
// speedup vs baseline: 1.8031x; 1.8031x over previous
#include <cuda_runtime.h>
#include <cuda_bf16.h>
#include <cstdint>

// ---------------- problem constants ----------------
#define B_    4
#define N_    1024
#define CIN_  256
#define HW_   256
#define D_    512
#define IN_   2304
#define ROWS_ 4096

// ---------------- device scratch ----------------
__device__ float g_featsT[(size_t)B_ * HW_ * HW_ * CIN_]; // NHWC, 256 MB
__device__ float g_bbox[ROWS_ * 4];
__device__ __nv_bfloat16 g_flat_hi[(size_t)ROWS_ * IN_];
__device__ __nv_bfloat16 g_flat_lo[(size_t)ROWS_ * IN_];
__device__ __nv_bfloat16 g_w1t_hi[(size_t)D_ * IN_];
__device__ __nv_bfloat16 g_w1t_lo[(size_t)D_ * IN_];
__device__ __nv_bfloat16 g_w2t_hi[(size_t)D_ * D_];
__device__ __nv_bfloat16 g_w2t_lo[(size_t)D_ * D_];
__device__ __nv_bfloat16 g_hid_hi[(size_t)ROWS_ * D_];
__device__ __nv_bfloat16 g_hid_lo[(size_t)ROWS_ * D_];
__device__ float g_lines[(size_t)ROWS_ * D_];
__device__ float g_outt[(size_t)ROWS_ * D_];

// ---------------- helpers ----------------
#define CP_ASYNC16(dst, src) \
    asm volatile("cp.async.cg.shared.global [%0], [%1], 16;" :: "r"(dst), "l"(src))
#define CP_COMMIT() asm volatile("cp.async.commit_group;" ::: "memory")
#define CP_WAIT(n)  asm volatile("cp.async.wait_group %0;" :: "n"(n) : "memory")

__device__ __forceinline__ void mma16816(float* c, const uint32_t* a, const uint32_t* b) {
    asm volatile(
        "mma.sync.aligned.m16n8k16.row.col.f32.bf16.bf16.f32 "
        "{%0,%1,%2,%3}, {%4,%5,%6,%7}, {%8,%9}, {%0,%1,%2,%3};"
        : "+f"(c[0]), "+f"(c[1]), "+f"(c[2]), "+f"(c[3])
        : "r"(a[0]), "r"(a[1]), "r"(a[2]), "r"(a[3]), "r"(b[0]), "r"(b[1]));
}

__device__ __forceinline__ uint32_t pack_bf16(float x, float y) {
    __nv_bfloat16 hx = __float2bfloat16(x);
    __nv_bfloat16 hy = __float2bfloat16(y);
    return (uint32_t)__bfloat16_as_ushort(hx) | ((uint32_t)__bfloat16_as_ushort(hy) << 16);
}

// ---------------- kernel 1: bbox ----------------
__global__ void bbox_kernel(const float* __restrict__ boxes) {
    int n = blockIdx.x * blockDim.x + threadIdx.x;
    if (n >= ROWS_) return;
    const float* p = boxes + (size_t)n * 8;
    float x0 = p[0], y0 = p[1], x1 = p[2], y1 = p[3];
    float x2 = p[4], y2 = p[5], x3 = p[6], y3 = p[7];
    g_bbox[n * 4 + 0] = fminf(fminf(x0, x1), fminf(x2, x3));
    g_bbox[n * 4 + 1] = fminf(fminf(y0, y1), fminf(y2, y3));
    g_bbox[n * 4 + 2] = fmaxf(fmaxf(x0, x1), fmaxf(x2, x3));
    g_bbox[n * 4 + 3] = fmaxf(fmaxf(y0, y1), fmaxf(y2, y3));
}

// ---------------- kernel 2: NCHW -> NHWC transpose ----------------
__global__ void feat_transpose_kernel(const float* __restrict__ in) {
    __shared__ float tile[32][33];
    int b  = blockIdx.z;
    int p0 = blockIdx.x * 32;
    int c0 = blockIdx.y * 32;
    const float* ib = in + (size_t)b * CIN_ * (HW_ * HW_);
    float* ob = g_featsT + (size_t)b * (HW_ * HW_) * CIN_;
    int tx = threadIdx.x, ty = threadIdx.y;
#pragma unroll
    for (int i = 0; i < 4; i++)
        tile[ty + i * 8][tx] = ib[(size_t)(c0 + ty + i * 8) * (HW_ * HW_) + p0 + tx];
    __syncthreads();
#pragma unroll
    for (int i = 0; i < 4; i++)
        ob[(size_t)(p0 + ty + i * 8) * CIN_ + c0 + tx] = tile[tx][ty + i * 8];
}

// ---------------- kernel 2b: weight transpose + bf16 hi/lo split ----------
// W: [K][512] f32 row-major -> T{hi,lo}: [512][K] bf16
__global__ void wsplit_kernel(const float* __restrict__ W,
                              __nv_bfloat16* __restrict__ Thi,
                              __nv_bfloat16* __restrict__ Tlo, int K) {
    __shared__ float tile[32][33];
    int k0 = blockIdx.x * 32, n0 = blockIdx.y * 32;
    int tx = threadIdx.x, ty = threadIdx.y;
#pragma unroll
    for (int i = 0; i < 4; i++)
        tile[ty + i * 8][tx] = W[(size_t)(k0 + ty + i * 8) * D_ + n0 + tx];
    __syncthreads();
#pragma unroll
    for (int i = 0; i < 4; i++) {
        float v = tile[tx][ty + i * 8];
        __nv_bfloat16 hi = __float2bfloat16(v);
        size_t idx = (size_t)(n0 + ty + i * 8) * K + k0 + tx;
        Thi[idx] = hi;
        Tlo[idx] = __float2bfloat16(v - __bfloat162float(hi));
    }
}

// ---------------- kernel 3: ROI align -> bf16 hi/lo flat ----------------
__global__ __launch_bounds__(256) void roi_kernel() {
    int n = blockIdx.x;
    int b = n >> 10;
    int c = threadIdx.x;
    const float* fb = g_featsT + (size_t)b * (HW_ * HW_) * CIN_;

    float4 bb = *(const float4*)(g_bbox + n * 4);
    float x1 = bb.x * 0.25f, y1 = bb.y * 0.25f;
    float x2 = bb.z * 0.25f, y2 = bb.w * 0.25f;
    float binw = fmaxf(x2 - x1, 1.0f) * (1.0f / 3.0f);
    float binh = fmaxf(y2 - y1, 1.0f) * (1.0f / 3.0f);

    int   yi0[6], yi1[6], xi0[6], xi1[6];
    float yl[6], yv[6], xl[6], xv[6];
#pragma unroll
    for (int s = 0; s < 6; s++) {
        float g = 0.5f * (float)s + 0.25f;
        float yy = y1 + g * binh;
        yv[s] = (yy > -1.0f && yy < 256.0f) ? 1.0f : 0.0f;
        float yc = fminf(fmaxf(yy, 0.0f), 255.0f);
        int i0 = (int)floorf(yc);
        yi0[s] = i0; yi1[s] = min(i0 + 1, 255); yl[s] = yc - (float)i0;

        float xx = x1 + g * binw;
        xv[s] = (xx > -1.0f && xx < 256.0f) ? 1.0f : 0.0f;
        float xc = fminf(fmaxf(xx, 0.0f), 255.0f);
        int j0 = (int)floorf(xc);
        xi0[s] = j0; xi1[s] = min(j0 + 1, 255); xl[s] = xc - (float)j0;
    }

    float acc[9];
#pragma unroll
    for (int i = 0; i < 9; i++) acc[i] = 0.0f;

#pragma unroll
    for (int sy = 0; sy < 6; sy++) {
        float ly = yl[sy], hy = 1.0f - ly;
        int r0 = yi0[sy] * 256, r1 = yi1[sy] * 256;
#pragma unroll
        for (int sx = 0; sx < 6; sx++) {
            float lx = xl[sx], hx = 1.0f - lx;
            float w = 0.25f * yv[sy] * xv[sx];
            const float* p00 = fb + ((size_t)(r0 + xi0[sx])) * CIN_ + c;
            const float* p01 = fb + ((size_t)(r0 + xi1[sx])) * CIN_ + c;
            const float* p10 = fb + ((size_t)(r1 + xi0[sx])) * CIN_ + c;
            const float* p11 = fb + ((size_t)(r1 + xi1[sx])) * CIN_ + c;
            float v = __ldg(p00) * (hy * hx) + __ldg(p01) * (hy * lx)
                    + __ldg(p10) * (ly * hx) + __ldg(p11) * (ly * lx);
            acc[(sy >> 1) * 3 + (sx >> 1)] += v * w;
        }
    }

    __shared__ float st[IN_];
#pragma unroll
    for (int i = 0; i < 9; i++) st[c * 9 + i] = acc[i];
    __syncthreads();
    size_t base = (size_t)n * IN_;
    for (int i = c; i < IN_; i += 256) {
        float v = st[i];
        __nv_bfloat16 hi = __float2bfloat16(v);
        g_flat_hi[base + i] = hi;
        g_flat_lo[base + i] = __float2bfloat16(v - __bfloat162float(hi));
    }
}

// ---------------- kernel 4/5: mma.sync bf16 hi/lo GEMM -------------------
// CTA tile 128x128x32; 8 warps, each 64x32 (m16n8k16 grid 4x4x2).
// MODE 0: hid{hi,lo} = relu(flat @ W1 + b1)   (K = 2304)
// MODE 1: g_lines    = hid @ W2 + b2          (K = 512)
#define SROW 40              // smem row stride in bf16 elems (80 B, conflict-free)
#define STAGE_BYTES (128 * SROW * 2)  // 10240 B per tile

template <int MODE>
__global__ __launch_bounds__(256) void mma_gemm_kernel(const float* __restrict__ bias) {
    constexpr int K  = (MODE == 0) ? IN_ : D_;
    constexpr int KT = K / 32;
    constexpr int T  = 3 * KT;

    const __nv_bfloat16* Ahi = (MODE == 0) ? g_flat_hi : g_hid_hi;
    const __nv_bfloat16* Alo = (MODE == 0) ? g_flat_lo : g_hid_lo;
    const __nv_bfloat16* Bhi = (MODE == 0) ? g_w1t_hi : g_w2t_hi;
    const __nv_bfloat16* Blo = (MODE == 0) ? g_w1t_lo : g_w2t_lo;

    __shared__ __align__(16) char smem[4 * STAGE_BYTES];  // {A0,B0,A1,B1}
    const uint32_t sbase = (uint32_t)__cvta_generic_to_shared(smem);

    const int tid  = threadIdx.x;
    const int wid  = tid >> 5, lane = tid & 31;
    const int g    = lane >> 2, tg = lane & 3;
    const int wm   = wid >> 2, wn = wid & 3;       // warp grid 2 x 4
    const int bm   = blockIdx.y * 128;
    const int bn   = blockIdx.x * 128;

    const int lrow = tid >> 1;                     // 0..127
    const int lch  = (tid & 1) * 2;                // chunk base 0 or 2

    float acc[4][4][4];
#pragma unroll
    for (int i = 0; i < 4; i++)
#pragma unroll
        for (int j = 0; j < 4; j++)
#pragma unroll
            for (int q = 0; q < 4; q++) acc[i][j][q] = 0.0f;

    auto load_tile = [&](int t, int s) {
        int term = t / KT;
        int kk = (t - term * KT) * 32;
        const __nv_bfloat16* Asrc = (term == 2) ? Alo : Ahi;
        const __nv_bfloat16* Bsrc = (term == 1) ? Blo : Bhi;
        const char* Ag = (const char*)(Asrc + (size_t)(bm + lrow) * K + kk);
        const char* Bg = (const char*)(Bsrc + (size_t)(bn + lrow) * K + kk);
        uint32_t sa = sbase + s * 2 * STAGE_BYTES + lrow * (SROW * 2);
        uint32_t sb = sa + STAGE_BYTES;
        CP_ASYNC16(sa + (lch + 0) * 16, Ag + (lch + 0) * 16);
        CP_ASYNC16(sa + (lch + 1) * 16, Ag + (lch + 1) * 16);
        CP_ASYNC16(sb + (lch + 0) * 16, Bg + (lch + 0) * 16);
        CP_ASYNC16(sb + (lch + 1) * 16, Bg + (lch + 1) * 16);
    };

    load_tile(0, 0);
    CP_COMMIT();

    int buf = 0;
    for (int t = 0; t < T; t++) {
        if (t + 1 < T) { load_tile(t + 1, buf ^ 1); CP_COMMIT(); }
        if (t + 1 < T) { CP_WAIT(1); } else { CP_WAIT(0); }
        __syncthreads();

        const __nv_bfloat16* Asm = (const __nv_bfloat16*)(smem + buf * 2 * STAGE_BYTES);
        const __nv_bfloat16* Bsm = (const __nv_bfloat16*)(smem + buf * 2 * STAGE_BYTES + STAGE_BYTES);

#pragma unroll
        for (int k16 = 0; k16 < 32; k16 += 16) {
            uint32_t a[4][4], b[4][2];
#pragma unroll
            for (int mt = 0; mt < 4; mt++) {
                const __nv_bfloat16* p = Asm + (size_t)(wm * 64 + mt * 16 + g) * SROW + k16 + tg * 2;
                a[mt][0] = *(const uint32_t*)(p);
                a[mt][1] = *(const uint32_t*)(p + 8 * SROW);
                a[mt][2] = *(const uint32_t*)(p + 8);
                a[mt][3] = *(const uint32_t*)(p + 8 * SROW + 8);
            }
#pragma unroll
            for (int nt = 0; nt < 4; nt++) {
                const __nv_bfloat16* p = Bsm + (size_t)(wn * 32 + nt * 8 + g) * SROW + k16 + tg * 2;
                b[nt][0] = *(const uint32_t*)(p);
                b[nt][1] = *(const uint32_t*)(p + 8);
            }
#pragma unroll
            for (int mt = 0; mt < 4; mt++)
#pragma unroll
                for (int nt = 0; nt < 4; nt++)
                    mma16816(acc[mt][nt], a[mt], b[nt]);
        }
        __syncthreads();
        buf ^= 1;
    }

    // ---------------- epilogue ----------------
#pragma unroll
    for (int mt = 0; mt < 4; mt++) {
        const int row = bm + wm * 64 + mt * 16 + g;
#pragma unroll
        for (int nt = 0; nt < 4; nt++) {
            const int col = bn + wn * 32 + nt * 8 + 2 * tg;
            float bc0 = bias[col], bc1 = bias[col + 1];
            float v0 = acc[mt][nt][0] + bc0;
            float v1 = acc[mt][nt][1] + bc1;
            float v2 = acc[mt][nt][2] + bc0;
            float v3 = acc[mt][nt][3] + bc1;
            if (MODE == 0) {
                v0 = fmaxf(v0, 0.0f); v1 = fmaxf(v1, 0.0f);
                v2 = fmaxf(v2, 0.0f); v3 = fmaxf(v3, 0.0f);
                __nv_bfloat16 h0 = __float2bfloat16(v0), h1 = __float2bfloat16(v1);
                __nv_bfloat16 h2 = __float2bfloat16(v2), h3 = __float2bfloat16(v3);
                uint32_t hi01 = (uint32_t)__bfloat16_as_ushort(h0) |
                                ((uint32_t)__bfloat16_as_ushort(h1) << 16);
                uint32_t hi23 = (uint32_t)__bfloat16_as_ushort(h2) |
                                ((uint32_t)__bfloat16_as_ushort(h3) << 16);
                uint32_t lo01 = pack_bf16(v0 - __bfloat162float(h0), v1 - __bfloat162float(h1));
                uint32_t lo23 = pack_bf16(v2 - __bfloat162float(h2), v3 - __bfloat162float(h3));
                *(uint32_t*)(g_hid_hi + (size_t)row * D_ + col)       = hi01;
                *(uint32_t*)(g_hid_lo + (size_t)row * D_ + col)       = lo01;
                *(uint32_t*)(g_hid_hi + (size_t)(row + 8) * D_ + col) = hi23;
                *(uint32_t*)(g_hid_lo + (size_t)(row + 8) * D_ + col) = lo23;
            } else {
                *(float2*)(g_lines + (size_t)row * D_ + col)       = make_float2(v0, v1);
                *(float2*)(g_lines + (size_t)(row + 8) * D_ + col) = make_float2(v2, v3);
            }
        }
    }
}

// ---------------- kernel 6: pos embed + LN1 + add + LN2 ----------------
__device__ __forceinline__ float2 block_reduce2(float v0, float v1) {
    __shared__ float s0[16], s1[16];
    int lane = threadIdx.x & 31, wid = threadIdx.x >> 5;
    __syncthreads();
#pragma unroll
    for (int o = 16; o > 0; o >>= 1) {
        v0 += __shfl_down_sync(0xffffffffu, v0, o);
        v1 += __shfl_down_sync(0xffffffffu, v1, o);
    }
    if (lane == 0) { s0[wid] = v0; s1[wid] = v1; }
    __syncthreads();
    if (wid == 0) {
        v0 = (lane < 16) ? s0[lane] : 0.0f;
        v1 = (lane < 16) ? s1[lane] : 0.0f;
#pragma unroll
        for (int o = 8; o > 0; o >>= 1) {
            v0 += __shfl_down_sync(0xffffffffu, v0, o);
            v1 += __shfl_down_sync(0xffffffffu, v1, o);
        }
        if (lane == 0) { s0[0] = v0; s1[0] = v1; }
    }
    __syncthreads();
    return make_float2(s0[0], s1[0]);
}

__global__ __launch_bounds__(512) void posln_kernel(
    const float* __restrict__ img_sizes,
    const float* __restrict__ Wb, const float* __restrict__ bbv,
    const float* __restrict__ g1, const float* __restrict__ be1,
    const float* __restrict__ g2, const float* __restrict__ be2) {
    int n = blockIdx.x;
    int b = n >> 10;
    int d = threadIdx.x;

    float s0 = img_sizes[2 * b], s1 = img_sizes[2 * b + 1];
    float q0 = g_bbox[n * 4 + 0] / s0;
    float q1 = g_bbox[n * 4 + 1] / s1;
    float q2 = g_bbox[n * 4 + 2] / s0;
    float q3 = g_bbox[n * 4 + 3] / s1;

    float p = bbv[d] + q0 * Wb[d] + q1 * Wb[D_ + d] + q2 * Wb[2 * D_ + d] + q3 * Wb[3 * D_ + d];
    float2 r = block_reduce2(p, p * p);
    float mu  = r.x * (1.0f / D_);
    float var = r.y * (1.0f / D_) - mu * mu;
    float pos = (p - mu) * rsqrtf(var + 1e-5f) * g1[d] + be1[d];

    float sf = g_lines[(size_t)n * D_ + d] + pos;
    r = block_reduce2(sf, sf * sf);
    mu  = r.x * (1.0f / D_);
    var = r.y * (1.0f / D_) - mu * mu;
    float o = (sf - mu) * rsqrtf(var + 1e-5f) * g2[d] + be2[d];
    g_outt[(size_t)n * D_ + d] = o;
}

// ---------------- kernel 7: (B,N,D) -> (B,D,N) ----------------
__global__ void out_transpose_kernel(float* __restrict__ out) {
    __shared__ float tile[32][33];
    int b  = blockIdx.z;
    int n0 = blockIdx.x * 32;
    int d0 = blockIdx.y * 32;
    int tx = threadIdx.x, ty = threadIdx.y;
#pragma unroll
    for (int i = 0; i < 4; i++)
        tile[ty + i * 8][tx] = g_outt[((size_t)(b << 10) + n0 + ty + i * 8) * D_ + d0 + tx];
    __syncthreads();
#pragma unroll
    for (int i = 0; i < 4; i++)
        out[((size_t)b * D_ + d0 + ty + i * 8) * N_ + n0 + tx] = tile[tx][ty + i * 8];
}

// ---------------- kernel 8: masks = 1 ----------------
__global__ void masks_kernel(float* __restrict__ m) {
    int i = blockIdx.x * blockDim.x + threadIdx.x;
    if (i < B_ * N_) m[i] = 1.0f;
}

// ---------------- launch ----------------
extern "C" void kernel_launch(void* const* d_in, const int* in_sizes, int n_in,
                              void* d_out, int out_size) {
    const float* feats     = (const float*)d_in[0];
    const float* boxes     = (const float*)d_in[1];
    const float* img_sizes = (const float*)d_in[2];
    const float* W1 = (const float*)d_in[3];
    const float* b1 = (const float*)d_in[4];
    const float* W2 = (const float*)d_in[5];
    const float* b2 = (const float*)d_in[6];
    const float* Wb = (const float*)d_in[7];
    const float* bb = (const float*)d_in[8];
    const float* g1 = (const float*)d_in[9];
    const float* be1 = (const float*)d_in[10];
    const float* g2 = (const float*)d_in[11];
    const float* be2 = (const float*)d_in[12];
    float* out = (float*)d_out;

    __nv_bfloat16 *w1h, *w1l, *w2h, *w2l;
    cudaGetSymbolAddress((void**)&w1h, g_w1t_hi);
    cudaGetSymbolAddress((void**)&w1l, g_w1t_lo);
    cudaGetSymbolAddress((void**)&w2h, g_w2t_hi);
    cudaGetSymbolAddress((void**)&w2l, g_w2t_lo);

    bbox_kernel<<<16, 256>>>(boxes);
    feat_transpose_kernel<<<dim3(2048, 8, 4), dim3(32, 8)>>>(feats);
    wsplit_kernel<<<dim3(IN_ / 32, D_ / 32), dim3(32, 8)>>>(W1, w1h, w1l, IN_);
    wsplit_kernel<<<dim3(D_ / 32, D_ / 32), dim3(32, 8)>>>(W2, w2h, w2l, D_);
    roi_kernel<<<ROWS_, 256>>>();
    mma_gemm_kernel<0><<<dim3(D_ / 128, ROWS_ / 128), 256>>>(b1);
    mma_gemm_kernel<1><<<dim3(D_ / 128, ROWS_ / 128), 256>>>(b2);
    posln_kernel<<<ROWS_, 512>>>(img_sizes, Wb, bb, g1, be1, g2, be2);
    out_transpose_kernel<<<dim3(32, 16, 4), dim3(32, 8)>>>(out);
    masks_kernel<<<16, 256>>>(out + (size_t)B_ * D_ * N_);
}